// round 1
// baseline (speedup 1.0000x reference)
#include <cuda_runtime.h>

// Problem constants (fixed by the reference)
#define Bc 16
#define Lc 512
#define Hc 8
#define Ec 64
#define Dc 64

// Tiling
#define BM 32            // query rows per CTA
#define BN 128           // key/value rows per smem tile
#define THREADS 256
#define SSTRIDE 516      // padded row stride for score buffer (L + 4)
#define KSTRIDE 68       // padded row stride for K/V/Q tiles (64 + 4)

__global__ __launch_bounds__(THREADS) void anomaly_attn_kernel(
    const float* __restrict__ Q, const float* __restrict__ K,
    const float* __restrict__ V, const float* __restrict__ sigma,
    const float* __restrict__ gate_logit, float* __restrict__ out)
{
    extern __shared__ float sm[];
    float* sS  = sm;                         // BM * SSTRIDE  (scores -> probs)
    float* sKV = sS + BM * SSTRIDE;          // BN * KSTRIDE  (K tile, then V tile)
    float* sQ  = sKV + BN * KSTRIDE;         // BM * KSTRIDE

    const int t  = threadIdx.x;
    const int l0 = blockIdx.x * BM;
    const int bh = blockIdx.y;
    const int b  = bh >> 3;
    const int h  = bh & 7;

    const size_t rowstride = (size_t)Hc * Ec;  // 512 floats between consecutive seq positions
    const float* Qb = Q + ((size_t)b * Lc) * rowstride + (size_t)h * Ec;
    const float* Kb = K + ((size_t)b * Lc) * rowstride + (size_t)h * Ec;
    const float* Vb = V + ((size_t)b * Lc) * rowstride + (size_t)h * Dc;

    // ---- load Q tile (pre-scaled by 1/sqrt(E)) ----
    const float scale = 0.125f;
    for (int i = t; i < BM * 16; i += THREADS) {
        int r = i >> 4, c = (i & 15) << 2;
        float4 v = *(const float4*)(Qb + (size_t)(l0 + r) * rowstride + c);
        float* dst = sQ + r * KSTRIDE + c;
        dst[0] = v.x * scale; dst[1] = v.y * scale;
        dst[2] = v.z * scale; dst[3] = v.w * scale;
    }

    // ---- phase 1: scores = (Q*scale) K^T, causal-masked, into sS ----
    const int tx = t & 15, ty = t >> 4;
    const int r0 = ty * 2, c0 = tx * 8;

    for (int st = 0; st < Lc; st += BN) {
        __syncthreads();
        for (int i = t; i < BN * 16; i += THREADS) {
            int r = i >> 4, c = (i & 15) << 2;
            float4 v = *(const float4*)(Kb + (size_t)(st + r) * rowstride + c);
            float* dst = sKV + r * KSTRIDE + c;
            dst[0] = v.x; dst[1] = v.y; dst[2] = v.z; dst[3] = v.w;
        }
        __syncthreads();

        float acc[2][8];
        #pragma unroll
        for (int i = 0; i < 2; i++)
            #pragma unroll
            for (int j = 0; j < 8; j++) acc[i][j] = 0.f;

        #pragma unroll 4
        for (int e = 0; e < Ec; e++) {
            float a0 = sQ[r0 * KSTRIDE + e];
            float a1 = sQ[(r0 + 1) * KSTRIDE + e];
            #pragma unroll
            for (int j = 0; j < 8; j++) {
                float bv = sKV[(c0 + j) * KSTRIDE + e];
                acc[0][j] = fmaf(a0, bv, acc[0][j]);
                acc[1][j] = fmaf(a1, bv, acc[1][j]);
            }
        }

        #pragma unroll
        for (int rr = 0; rr < 2; rr++) {
            int l = l0 + r0 + rr;
            float* row = sS + (r0 + rr) * SSTRIDE + st + c0;
            #pragma unroll
            for (int j = 0; j < 8; j++)
                row[j] = (st + c0 + j <= l) ? acc[rr][j] : -1e30f;
        }
    }
    __syncthreads();

    // ---- phase 2: per-row softmax + Gaussian prior + gated fuse + renorm ----
    const int warp = t >> 5, lane = t & 31;
    const float g = 1.f / (1.f + __expf(-__ldg(gate_logit + h)));

    for (int rr = warp; rr < BM; rr += 8) {
        const int l = l0 + rr;
        float* row = sS + rr * SSTRIDE;

        float m = -1e30f;
        for (int s = lane; s < Lc; s += 32) m = fmaxf(m, row[s]);
        #pragma unroll
        for (int o = 16; o; o >>= 1) m = fmaxf(m, __shfl_xor_sync(0xffffffffu, m, o));

        float Z = 0.f;
        for (int s = lane; s < Lc; s += 32) {
            float e = __expf(row[s] - m);   // masked (-1e30) -> 0
            row[s] = e;
            Z += e;
        }
        #pragma unroll
        for (int o = 16; o; o >>= 1) Z += __shfl_xor_sync(0xffffffffu, Z, o);

        // sigma transform: sig = 3^(sigmoid(5*sigma)+1e-5) - 1
        float sg = sigma[((size_t)b * Lc + l) * Hc + h];
        float sig = 1.f / (1.f + __expf(-5.f * sg)) + 1e-5f;
        sig = exp2f(sig * 1.5849625007211562f) - 1.f;
        const float inv2s2 = 1.f / (2.f * sig * sig);
        const float coef = 0.3989422804014327f / sig;  // 1/(sqrt(2pi)*sig)

        float Sp = 0.f;
        for (int s = lane; s < Lc; s += 32) {
            float d = (float)(l - s);
            Sp += __expf(-d * d * inv2s2);
        }
        #pragma unroll
        for (int o = 16; o; o >>= 1) Sp += __shfl_xor_sync(0xffffffffu, Sp, o);
        Sp *= coef;

        // fused = (g*series + (1-g)*prior/(Sp+1e-8)) / (Sf+1e-8), Sf = g + (1-g)*Sp/(Sp+1e-8)
        float Sf = g + (1.f - g) * (Sp / (Sp + 1e-8f));
        float invSf = 1.f / (Sf + 1e-8f);
        float wE = (g / Z) * invSf;
        float wP = ((1.f - g) * coef / (Sp + 1e-8f)) * invSf;

        for (int s = lane; s < Lc; s += 32) {
            float d = (float)(l - s);
            float p = __expf(-d * d * inv2s2);
            row[s] = row[s] * wE + p * wP;
        }
    }
    __syncthreads();

    // ---- phase 3: out = P @ V ----
    const int r  = t >> 3;
    const int d0 = (t & 7) * 8;
    float acc[8];
    #pragma unroll
    for (int j = 0; j < 8; j++) acc[j] = 0.f;

    for (int st = 0; st < Lc; st += BN) {
        __syncthreads();
        for (int i = t; i < BN * 16; i += THREADS) {
            int rr = i >> 4, c = (i & 15) << 2;
            float4 v = *(const float4*)(Vb + (size_t)(st + rr) * rowstride + c);
            float* dst = sKV + rr * KSTRIDE + c;
            dst[0] = v.x; dst[1] = v.y; dst[2] = v.z; dst[3] = v.w;
        }
        __syncthreads();

        const float* prow = sS + r * SSTRIDE + st;
        #pragma unroll 4
        for (int s = 0; s < BN; s++) {
            float a = prow[s];
            float4 v0 = *(const float4*)(sKV + s * KSTRIDE + d0);
            float4 v1 = *(const float4*)(sKV + s * KSTRIDE + d0 + 4);
            acc[0] = fmaf(a, v0.x, acc[0]);
            acc[1] = fmaf(a, v0.y, acc[1]);
            acc[2] = fmaf(a, v0.z, acc[2]);
            acc[3] = fmaf(a, v0.w, acc[3]);
            acc[4] = fmaf(a, v1.x, acc[4]);
            acc[5] = fmaf(a, v1.y, acc[5]);
            acc[6] = fmaf(a, v1.z, acc[6]);
            acc[7] = fmaf(a, v1.w, acc[7]);
        }
    }

    // out[b, l, h, d]
    float* ob = out + (((size_t)b * Lc + (l0 + r)) * Hc + h) * Dc + d0;
    *(float4*)(ob)     = make_float4(acc[0], acc[1], acc[2], acc[3]);
    *(float4*)(ob + 4) = make_float4(acc[4], acc[5], acc[6], acc[7]);
}

extern "C" void kernel_launch(void* const* d_in, const int* in_sizes, int n_in,
                              void* d_out, int out_size)
{
    const float* Q     = (const float*)d_in[0];
    const float* K     = (const float*)d_in[1];
    const float* V     = (const float*)d_in[2];
    const float* sigma = (const float*)d_in[3];
    const float* gate  = (const float*)d_in[4];
    // d_in[5] = attn_mask: deterministic causal triu(k=1); recomputed analytically, unused.
    float* out = (float*)d_out;

    const size_t smem = (size_t)(BM * SSTRIDE + BN * KSTRIDE + BM * KSTRIDE) * sizeof(float);
    cudaFuncSetAttribute(anomaly_attn_kernel,
                         cudaFuncAttributeMaxDynamicSharedMemorySize, (int)smem);

    dim3 grid(Lc / BM, Bc * Hc);
    anomaly_attn_kernel<<<grid, THREADS, smem>>>(Q, K, V, sigma, gate, out);
}

// round 2
// speedup vs baseline: 3.6729x; 3.6729x over previous
#include <cuda_runtime.h>

// Problem constants (fixed by the reference)
#define Bc 16
#define Lc 512
#define Hc 8
#define Ec 64
#define Dc 64

// Tiling
#define BM 32            // query rows per CTA
#define BN 128           // key/value rows per smem tile
#define THREADS 256
#define SSTRIDE 516      // padded row stride for score buffer (L + 4)
#define QS 68            // Q tile row stride
#define KTS 132          // transposed-K tile row stride (BN + 4)
#define VS 68            // V tile row stride
#define TBUF 8704        // max(64*KTS=8448, BN*VS=8704)

__global__ __launch_bounds__(THREADS, 2) void anomaly_attn_kernel(
    const float* __restrict__ Q, const float* __restrict__ K,
    const float* __restrict__ V, const float* __restrict__ sigma,
    const float* __restrict__ gate_logit, float* __restrict__ out)
{
    extern __shared__ float sm[];
    float* sS = sm;                   // BM * SSTRIDE  (scores -> probs)
    float* sT = sS + BM * SSTRIDE;    // TBUF: K^T tile (phase 1) / V tile (phase 3)
    float* sQ = sT + TBUF;            // BM * QS

    const int t  = threadIdx.x;
    const int l0 = blockIdx.x * BM;
    const int bh = blockIdx.y;
    const int b  = bh >> 3;
    const int h  = bh & 7;

    const size_t rowstride = (size_t)Hc * Ec;  // 512 floats between seq positions
    const float* Qb = Q + ((size_t)b * Lc) * rowstride + (size_t)h * Ec;
    const float* Kb = K + ((size_t)b * Lc) * rowstride + (size_t)h * Ec;
    const float* Vb = V + ((size_t)b * Lc) * rowstride + (size_t)h * Dc;

    // ---- load Q tile (pre-scaled by 1/sqrt(E)), coalesced ----
    const float scale = 0.125f;
    for (int i = t; i < BM * 16; i += THREADS) {
        int r = i >> 4, c = (i & 15) << 2;
        float4 v = *(const float4*)(Qb + (size_t)(l0 + r) * rowstride + c);
        float* dst = sQ + r * QS + c;
        dst[0] = v.x * scale; dst[1] = v.y * scale;
        dst[2] = v.z * scale; dst[3] = v.w * scale;
    }

    // ---- phase 1: scores = (Q*scale) K^T, causal-masked, into sS ----
    const int tx = t & 15, ty = t >> 4;
    const int r0 = ty * 2;
    const int cA = tx * 4, cB = cA + 64;

    for (int st = 0; st < Lc; st += BN) {
        __syncthreads();
        // load K tile TRANSPOSED: sT[e][s].  Contiguous smem stores (no conflicts);
        // global reads are 16B-per-row scattered but L2-resident (K reused 16x).
        for (int i = t; i < BN * 16; i += THREADS) {
            int r  = i & 127;
            int e4 = (i >> 7) << 2;
            float4 v = *(const float4*)(Kb + (size_t)(st + r) * rowstride + e4);
            sT[(e4 + 0) * KTS + r] = v.x;
            sT[(e4 + 1) * KTS + r] = v.y;
            sT[(e4 + 2) * KTS + r] = v.z;
            sT[(e4 + 3) * KTS + r] = v.w;
        }
        __syncthreads();

        float acc[2][8];
        #pragma unroll
        for (int i = 0; i < 2; i++)
            #pragma unroll
            for (int j = 0; j < 8; j++) acc[i][j] = 0.f;

        const float* qa = sQ + r0 * QS;
        for (int e = 0; e < Ec; e += 4) {
            float4 A0 = *(const float4*)(qa + e);
            float4 A1 = *(const float4*)(qa + QS + e);
            float a0[4] = {A0.x, A0.y, A0.z, A0.w};
            float a1[4] = {A1.x, A1.y, A1.z, A1.w};
            #pragma unroll
            for (int k = 0; k < 4; k++) {
                const float* bp = sT + (e + k) * KTS;
                float4 bA = *(const float4*)(bp + cA);
                float4 bB = *(const float4*)(bp + cB);
                acc[0][0] = fmaf(a0[k], bA.x, acc[0][0]);
                acc[0][1] = fmaf(a0[k], bA.y, acc[0][1]);
                acc[0][2] = fmaf(a0[k], bA.z, acc[0][2]);
                acc[0][3] = fmaf(a0[k], bA.w, acc[0][3]);
                acc[0][4] = fmaf(a0[k], bB.x, acc[0][4]);
                acc[0][5] = fmaf(a0[k], bB.y, acc[0][5]);
                acc[0][6] = fmaf(a0[k], bB.z, acc[0][6]);
                acc[0][7] = fmaf(a0[k], bB.w, acc[0][7]);
                acc[1][0] = fmaf(a1[k], bA.x, acc[1][0]);
                acc[1][1] = fmaf(a1[k], bA.y, acc[1][1]);
                acc[1][2] = fmaf(a1[k], bA.z, acc[1][2]);
                acc[1][3] = fmaf(a1[k], bA.w, acc[1][3]);
                acc[1][4] = fmaf(a1[k], bB.x, acc[1][4]);
                acc[1][5] = fmaf(a1[k], bB.y, acc[1][5]);
                acc[1][6] = fmaf(a1[k], bB.z, acc[1][6]);
                acc[1][7] = fmaf(a1[k], bB.w, acc[1][7]);
            }
        }

        #pragma unroll
        for (int rr = 0; rr < 2; rr++) {
            const int l = l0 + r0 + rr;
            float* dst = sS + (r0 + rr) * SSTRIDE + st;
            float4 vA, vB;
            vA.x = (st + cA + 0 <= l) ? acc[rr][0] : -1e30f;
            vA.y = (st + cA + 1 <= l) ? acc[rr][1] : -1e30f;
            vA.z = (st + cA + 2 <= l) ? acc[rr][2] : -1e30f;
            vA.w = (st + cA + 3 <= l) ? acc[rr][3] : -1e30f;
            vB.x = (st + cB + 0 <= l) ? acc[rr][4] : -1e30f;
            vB.y = (st + cB + 1 <= l) ? acc[rr][5] : -1e30f;
            vB.z = (st + cB + 2 <= l) ? acc[rr][6] : -1e30f;
            vB.w = (st + cB + 3 <= l) ? acc[rr][7] : -1e30f;
            *(float4*)(dst + cA) = vA;
            *(float4*)(dst + cB) = vB;
        }
    }
    __syncthreads();

    // ---- phase 2: per-row softmax + Gaussian prior + gated fuse + renorm ----
    const int warp = t >> 5, lane = t & 31;
    const float g = 1.f / (1.f + __expf(-__ldg(gate_logit + h)));

    for (int rr = warp; rr < BM; rr += 8) {
        const int l = l0 + rr;
        float* row = sS + rr * SSTRIDE;

        float m = -1e30f;
        #pragma unroll
        for (int k = 0; k < 16; k++) m = fmaxf(m, row[lane + k * 32]);
        #pragma unroll
        for (int o = 16; o; o >>= 1) m = fmaxf(m, __shfl_xor_sync(0xffffffffu, m, o));

        float Z = 0.f;
        #pragma unroll
        for (int k = 0; k < 16; k++) {
            float e = __expf(row[lane + k * 32] - m);   // masked (-1e30) -> 0
            row[lane + k * 32] = e;
            Z += e;
        }
        #pragma unroll
        for (int o = 16; o; o >>= 1) Z += __shfl_xor_sync(0xffffffffu, Z, o);

        // sigma transform: sig = 3^(sigmoid(5*sigma)+1e-5) - 1
        float sg = sigma[((size_t)b * Lc + l) * Hc + h];
        float sig = 1.f / (1.f + __expf(-5.f * sg)) + 1e-5f;
        sig = exp2f(sig * 1.5849625007211562f) - 1.f;
        const float inv2s2 = 1.f / (2.f * sig * sig);
        const float coef = 0.3989422804014327f / sig;  // 1/(sqrt(2pi)*sig)

        float pv[16];
        float Sp = 0.f;
        #pragma unroll
        for (int k = 0; k < 16; k++) {
            float d = (float)(l - (lane + k * 32));
            pv[k] = __expf(-d * d * inv2s2);
            Sp += pv[k];
        }
        #pragma unroll
        for (int o = 16; o; o >>= 1) Sp += __shfl_xor_sync(0xffffffffu, Sp, o);
        Sp *= coef;

        // fused = (g*series + (1-g)*prior/(Sp+1e-8)) / (Sf+1e-8),
        // Sf = g + (1-g)*Sp/(Sp+1e-8)
        float Sf = g + (1.f - g) * (Sp / (Sp + 1e-8f));
        float invSf = 1.f / (Sf + 1e-8f);
        float wE = (g / Z) * invSf;
        float wP = ((1.f - g) * coef / (Sp + 1e-8f)) * invSf;

        #pragma unroll
        for (int k = 0; k < 16; k++)
            row[lane + k * 32] = row[lane + k * 32] * wE + pv[k] * wP;
    }

    // ---- phase 3: out = P @ V ----
    const int d0 = (t & 15) * 4;
    const int r3 = (t >> 4) * 2;
    float o0[4] = {0.f, 0.f, 0.f, 0.f};
    float o1[4] = {0.f, 0.f, 0.f, 0.f};

    for (int st = 0; st < Lc; st += BN) {
        __syncthreads();
        for (int i = t; i < BN * 16; i += THREADS) {
            int r = i >> 4, c = (i & 15) << 2;
            float4 v = *(const float4*)(Vb + (size_t)(st + r) * rowstride + c);
            float* dst = sT + r * VS + c;
            dst[0] = v.x; dst[1] = v.y; dst[2] = v.z; dst[3] = v.w;
        }
        __syncthreads();

        const float* p0 = sS + r3 * SSTRIDE + st;
        const float* p1 = p0 + SSTRIDE;
        #pragma unroll 2
        for (int s = 0; s < BN; s += 4) {
            float4 P0 = *(const float4*)(p0 + s);
            float4 P1 = *(const float4*)(p1 + s);
            float a0[4] = {P0.x, P0.y, P0.z, P0.w};
            float a1[4] = {P1.x, P1.y, P1.z, P1.w};
            #pragma unroll
            for (int k = 0; k < 4; k++) {
                float4 v = *(const float4*)(sT + (s + k) * VS + d0);
                o0[0] = fmaf(a0[k], v.x, o0[0]);
                o0[1] = fmaf(a0[k], v.y, o0[1]);
                o0[2] = fmaf(a0[k], v.z, o0[2]);
                o0[3] = fmaf(a0[k], v.w, o0[3]);
                o1[0] = fmaf(a1[k], v.x, o1[0]);
                o1[1] = fmaf(a1[k], v.y, o1[1]);
                o1[2] = fmaf(a1[k], v.z, o1[2]);
                o1[3] = fmaf(a1[k], v.w, o1[3]);
            }
        }
    }

    // out[b, l, h, d]
    float* ob0 = out + (((size_t)b * Lc + (l0 + r3)) * Hc + h) * Dc + d0;
    float* ob1 = ob0 + (size_t)Hc * Dc;
    *(float4*)ob0 = make_float4(o0[0], o0[1], o0[2], o0[3]);
    *(float4*)ob1 = make_float4(o1[0], o1[1], o1[2], o1[3]);
}

extern "C" void kernel_launch(void* const* d_in, const int* in_sizes, int n_in,
                              void* d_out, int out_size)
{
    const float* Q     = (const float*)d_in[0];
    const float* K     = (const float*)d_in[1];
    const float* V     = (const float*)d_in[2];
    const float* sigma = (const float*)d_in[3];
    const float* gate  = (const float*)d_in[4];
    // d_in[5] = attn_mask: deterministic causal triu(k=1); recomputed analytically.
    float* out = (float*)d_out;

    const size_t smem = (size_t)(BM * SSTRIDE + TBUF + BM * QS) * sizeof(float);
    cudaFuncSetAttribute(anomaly_attn_kernel,
                         cudaFuncAttributeMaxDynamicSharedMemorySize, (int)smem);

    dim3 grid(Lc / BM, Bc * Hc);
    anomaly_attn_kernel<<<grid, THREADS, smem>>>(Q, K, V, sigma, gate, out);
}

// round 3
// speedup vs baseline: 10.2961x; 2.8033x over previous
#include <cuda_runtime.h>
#include <cstdint>

// Problem constants (fixed by the reference)
#define Bc 16
#define Lc 512
#define Hc 8
#define Ec 64
#define Dc 64

#define THREADS 256
#define SSTRIDE 516      // score buffer row stride (L + 4)
#define QS 68            // Q tile stride   (bank = 4*gid + tig  -> conflict-free A frags)
#define KS 68            // K tile stride   (bank = 4*gid + tig  -> conflict-free B frags)
#define VS 72            // V tile stride   (bank = 8*tig + gid  -> conflict-free B frags)
#define TBUF (128 * VS)  // 9216 floats: K tile (128x68<=) / V tile (128x72) / reduction bufs

__device__ __forceinline__ uint32_t f2tf32(float x) {
    uint32_t r;
    asm("cvt.rna.tf32.f32 %0, %1;" : "=r"(r) : "f"(x));
    return r;
}
__device__ __forceinline__ uint32_t fbits(float x) { return __float_as_uint(x); }

__device__ __forceinline__ void mma_tf32(float c[4], const uint32_t a[4],
                                         uint32_t b0, uint32_t b1) {
    asm volatile(
        "mma.sync.aligned.m16n8k8.row.col.f32.tf32.tf32.f32 "
        "{%0,%1,%2,%3}, {%4,%5,%6,%7}, {%8,%9}, {%0,%1,%2,%3};"
        : "+f"(c[0]), "+f"(c[1]), "+f"(c[2]), "+f"(c[3])
        : "r"(a[0]), "r"(a[1]), "r"(a[2]), "r"(a[3]), "r"(b0), "r"(b1));
}

__global__ __launch_bounds__(THREADS, 2) void anomaly_attn_kernel(
    const float* __restrict__ Q, const float* __restrict__ K,
    const float* __restrict__ V, const float* __restrict__ sigma,
    const float* __restrict__ gate_logit, float* __restrict__ out)
{
    extern __shared__ float sm[];
    float* sS = sm;                     // 32 * SSTRIDE : scores -> fused probs (tf32 bits)
    float* sT = sS + 32 * SSTRIDE;      // TBUF : K tile / V tile / reduction buffers
    float* sQ = sT + TBUF;              // 32 * QS : Q (tf32 bits, pre-scaled)

    const int t    = threadIdx.x;
    const int lane = t & 31;
    const int wrp  = t >> 5;
    const int gid  = lane >> 2;   // groupID      (0..7)
    const int tig  = lane & 3;    // thread in group (0..3)

    const int l0 = blockIdx.x * 32;
    const int bh = blockIdx.y;
    const int b  = bh >> 3;
    const int h  = bh & 7;

    const size_t rowstride = (size_t)Hc * Ec;   // 512 floats between seq positions
    const float* Qb = Q + ((size_t)b * Lc) * rowstride + (size_t)h * Ec;
    const float* Kb = K + ((size_t)b * Lc) * rowstride + (size_t)h * Ec;
    const float* Vb = V + ((size_t)b * Lc) * rowstride + (size_t)h * Dc;

    // ---- stage Q tile: scaled by 1/8, tf32-rounded ----
    for (int i = t; i < 32 * 16; i += THREADS) {
        int r = i >> 4, c = (i & 15) << 2;
        float4 v = *(const float4*)(Qb + (size_t)(l0 + r) * rowstride + c);
        float* dst = sQ + r * QS + c;
        dst[0] = __uint_as_float(f2tf32(v.x * 0.125f));
        dst[1] = __uint_as_float(f2tf32(v.y * 0.125f));
        dst[2] = __uint_as_float(f2tf32(v.z * 0.125f));
        dst[3] = __uint_as_float(f2tf32(v.w * 0.125f));
    }
    __syncthreads();

    // ================= phase 1: S = (Q/8) K^T via tf32 mma =================
    // warp -> rows mb1*16..+16, cols ns0..ns0+32 within the current 128-col tile
    const int mb1 = wrp >> 2;
    const int ns0 = (wrp & 3) * 32;

    // preload all A fragments (Q) into registers: 8 k-steps x 4 regs
    uint32_t Af[8][4];
    {
        const int ra = mb1 * 16 + gid;
        #pragma unroll
        for (int ks = 0; ks < 8; ks++) {
            int c0 = ks * 8 + tig;
            Af[ks][0] = fbits(sQ[ra * QS + c0]);
            Af[ks][1] = fbits(sQ[(ra + 8) * QS + c0]);
            Af[ks][2] = fbits(sQ[ra * QS + c0 + 4]);
            Af[ks][3] = fbits(sQ[(ra + 8) * QS + c0 + 4]);
        }
    }

    // causal tile skipping: only tiles with st <= l0+31 can hold unmasked cols
    const int nsteps = (l0 >> 7) + 1;

    for (int st = 0; st < nsteps; st++) {
        __syncthreads();
        // stage K tile rows [st*128, st*128+128), tf32-rounded, row-major stride KS
        for (int i = t; i < 128 * 16; i += THREADS) {
            int r = i >> 4, c = (i & 15) << 2;
            float4 v = *(const float4*)(Kb + (size_t)(st * 128 + r) * rowstride + c);
            float* dst = sT + r * KS + c;
            dst[0] = __uint_as_float(f2tf32(v.x));
            dst[1] = __uint_as_float(f2tf32(v.y));
            dst[2] = __uint_as_float(f2tf32(v.z));
            dst[3] = __uint_as_float(f2tf32(v.w));
        }
        __syncthreads();

        float c[4][4];
        #pragma unroll
        for (int nt = 0; nt < 4; nt++)
            #pragma unroll
            for (int j = 0; j < 4; j++) c[nt][j] = 0.f;

        #pragma unroll
        for (int ks = 0; ks < 8; ks++) {
            #pragma unroll
            for (int nt = 0; nt < 4; nt++) {
                const float* bp = sT + (ns0 + nt * 8 + gid) * KS + ks * 8 + tig;
                mma_tf32(c[nt], Af[ks], fbits(bp[0]), fbits(bp[4]));
            }
        }

        // write raw scores (no masking needed: phase 2 predicates on s <= l)
        const int r0 = mb1 * 16 + gid;
        #pragma unroll
        for (int nt = 0; nt < 4; nt++) {
            int col = st * 128 + ns0 + nt * 8 + 2 * tig;
            *(float2*)(sS + r0 * SSTRIDE + col)       = make_float2(c[nt][0], c[nt][1]);
            *(float2*)(sS + (r0 + 8) * SSTRIDE + col) = make_float2(c[nt][2], c[nt][3]);
        }
    }
    __syncthreads();

    // ========== phase 2: softmax + Gaussian prior + gated fuse + renorm ==========
    const float g = 1.f / (1.f + __expf(-__ldg(gate_logit + h)));

    for (int rr = wrp; rr < 32; rr += 8) {
        const int l = l0 + rr;
        float* row = sS + rr * SSTRIDE;

        float m = -1e30f;
        #pragma unroll
        for (int k = 0; k < 16; k++) {
            int s = lane + k * 32;
            if (s <= l) m = fmaxf(m, row[s]);
        }
        #pragma unroll
        for (int o = 16; o; o >>= 1) m = fmaxf(m, __shfl_xor_sync(0xffffffffu, m, o));

        float Z = 0.f;
        #pragma unroll
        for (int k = 0; k < 16; k++) {
            int s = lane + k * 32;
            float e = (s <= l) ? __expf(row[s] - m) : 0.f;
            row[s] = e;
            Z += e;
        }
        #pragma unroll
        for (int o = 16; o; o >>= 1) Z += __shfl_xor_sync(0xffffffffu, Z, o);

        // sig = 3^(sigmoid(5*sigma)+1e-5) - 1
        float sg = sigma[((size_t)b * Lc + l) * Hc + h];
        float sig = 1.f / (1.f + __expf(-5.f * sg)) + 1e-5f;
        sig = exp2f(sig * 1.5849625007211562f) - 1.f;
        const float inv2s2 = 1.f / (2.f * sig * sig);
        const float coef = 0.3989422804014327f / sig;   // 1/(sqrt(2pi)*sig)

        float pv[16];
        float Sp = 0.f;
        #pragma unroll
        for (int k = 0; k < 16; k++) {
            float d = (float)(l - (lane + k * 32));
            pv[k] = __expf(-d * d * inv2s2);
            Sp += pv[k];
        }
        #pragma unroll
        for (int o = 16; o; o >>= 1) Sp += __shfl_xor_sync(0xffffffffu, Sp, o);
        Sp *= coef;

        // fused = (g*series + (1-g)*prior/(Sp+1e-8)) / (Sf+1e-8)
        float Sf = g + (1.f - g) * (Sp / (Sp + 1e-8f));
        float invSf = 1.f / (Sf + 1e-8f);
        float wE = (g / Z) * invSf;
        float wP = ((1.f - g) * coef / (Sp + 1e-8f)) * invSf;

        #pragma unroll
        for (int k = 0; k < 16; k++) {
            int s = lane + k * 32;
            float val = fmaf(row[s], wE, pv[k] * wP);
            row[s] = __uint_as_float(f2tf32(val));   // tf32 A-operand for phase 3
        }
    }

    // ================= phase 3: out = P @ V via tf32 mma =================
    // warp -> (kh, nb, mb): rows mb*16..+16, cols nb*32..+32, k-half kh within each tile
    const int kh = wrp >> 2;
    const int nb = (wrp >> 1) & 1;
    const int mb = wrp & 1;

    float c3[4][4];
    #pragma unroll
    for (int nt = 0; nt < 4; nt++)
        #pragma unroll
        for (int j = 0; j < 4; j++) c3[nt][j] = 0.f;

    for (int st = 0; st < 4; st++) {
        __syncthreads();
        // stage V tile rows [st*128, +128), tf32-rounded, stride VS
        for (int i = t; i < 128 * 16; i += THREADS) {
            int r = i >> 4, c = (i & 15) << 2;
            float4 v = *(const float4*)(Vb + (size_t)(st * 128 + r) * rowstride + c);
            float* dst = sT + r * VS + c;
            dst[0] = __uint_as_float(f2tf32(v.x));
            dst[1] = __uint_as_float(f2tf32(v.y));
            dst[2] = __uint_as_float(f2tf32(v.z));
            dst[3] = __uint_as_float(f2tf32(v.w));
        }
        __syncthreads();

        const int ra = mb * 16 + gid;
        #pragma unroll
        for (int ks = 0; ks < 8; ks++) {
            const int kk = kh * 64 + ks * 8;             // k offset within tile
            uint32_t a[4];
            const float* ap = sS + ra * SSTRIDE + st * 128 + kk + tig;
            a[0] = fbits(ap[0]);
            a[1] = fbits(ap[8 * SSTRIDE]);
            a[2] = fbits(ap[4]);
            a[3] = fbits(ap[8 * SSTRIDE + 4]);
            #pragma unroll
            for (int nt = 0; nt < 4; nt++) {
                const float* bp = sT + (kk + tig) * VS + nb * 32 + nt * 8 + gid;
                mma_tf32(c3[nt], a, fbits(bp[0]), fbits(bp[4 * VS]));
            }
        }
    }

    // cross-warp (kh) reduction through smem, then coalesced store
    __syncthreads();
    float* sR = sT + kh * (32 * 68);   // two 32x68 buffers inside sT
    {
        const int r0 = mb * 16 + gid;
        #pragma unroll
        for (int nt = 0; nt < 4; nt++) {
            int col = nb * 32 + nt * 8 + 2 * tig;
            *(float2*)(sR + r0 * 68 + col)       = make_float2(c3[nt][0], c3[nt][1]);
            *(float2*)(sR + (r0 + 8) * 68 + col) = make_float2(c3[nt][2], c3[nt][3]);
        }
    }
    __syncthreads();

    const float* sR0 = sT;
    const float* sR1 = sT + 32 * 68;
    for (int i = t; i < 512; i += THREADS) {     // 512 float4 slots = 32x64
        int r = i >> 4, c = (i & 15) << 2;
        const float* p0 = sR0 + r * 68 + c;
        const float* p1 = sR1 + r * 68 + c;
        float4 o;
        o.x = p0[0] + p1[0];
        o.y = p0[1] + p1[1];
        o.z = p0[2] + p1[2];
        o.w = p0[3] + p1[3];
        *(float4*)(out + (((size_t)b * Lc + (l0 + r)) * Hc + h) * Dc + c) = o;
    }
}

extern "C" void kernel_launch(void* const* d_in, const int* in_sizes, int n_in,
                              void* d_out, int out_size)
{
    const float* Q     = (const float*)d_in[0];
    const float* K     = (const float*)d_in[1];
    const float* V     = (const float*)d_in[2];
    const float* sigma = (const float*)d_in[3];
    const float* gate  = (const float*)d_in[4];
    // d_in[5] = attn_mask: deterministic causal triu(k=1); handled analytically.
    float* out = (float*)d_out;

    const size_t smem = (size_t)(32 * SSTRIDE + TBUF + 32 * QS) * sizeof(float);
    cudaFuncSetAttribute(anomaly_attn_kernel,
                         cudaFuncAttributeMaxDynamicSharedMemorySize, (int)smem);

    dim3 grid(Lc / 32, Bc * Hc);
    anomaly_attn_kernel<<<grid, THREADS, smem>>>(Q, K, V, sigma, gate, out);
}

// round 4
// speedup vs baseline: 11.6270x; 1.1293x over previous
#include <cuda_runtime.h>
#include <cstdint>

// Problem constants (fixed by the reference)
#define Bc 16
#define Lc 512
#define Hc 8
#define Ec 64
#define Dc 64

#define THREADS 256
#define SSTRIDE 516      // score buffer row stride (L + 4)
#define QS 68            // Q tile stride
#define KS 68            // K tile stride   (bank = 4*gid + tig  -> conflict-free B frags)
#define VS 72            // V tile stride   (bank = 8*tig + gid  -> conflict-free B frags)
#define TBUF (128 * VS)  // 9216 floats: K tile / V tile / 4 reduction buffers (32x72)

__device__ __forceinline__ uint32_t f2tf32(float x) {
    uint32_t r;
    asm("cvt.rna.tf32.f32 %0, %1;" : "=r"(r) : "f"(x));
    return r;
}
__device__ __forceinline__ uint32_t fbits(float x) { return __float_as_uint(x); }

__device__ __forceinline__ void mma_tf32(float c[4], const uint32_t a[4],
                                         uint32_t b0, uint32_t b1) {
    asm volatile(
        "mma.sync.aligned.m16n8k8.row.col.f32.tf32.tf32.f32 "
        "{%0,%1,%2,%3}, {%4,%5,%6,%7}, {%8,%9}, {%0,%1,%2,%3};"
        : "+f"(c[0]), "+f"(c[1]), "+f"(c[2]), "+f"(c[3])
        : "r"(a[0]), "r"(a[1]), "r"(a[2]), "r"(a[3]), "r"(b0), "r"(b1));
}

__device__ __forceinline__ void cp16(uint32_t dst, const float* src) {
    asm volatile("cp.async.ca.shared.global [%0], [%1], 16;" :: "r"(dst), "l"(src));
}
#define CP_COMMIT() asm volatile("cp.async.commit_group;")
#define CP_WAIT0()  asm volatile("cp.async.wait_group 0;" ::: "memory")

__global__ __launch_bounds__(THREADS, 2) void anomaly_attn_kernel(
    const float* __restrict__ Q, const float* __restrict__ K,
    const float* __restrict__ V, const float* __restrict__ sigma,
    const float* __restrict__ gate_logit, float* __restrict__ out)
{
    extern __shared__ float sm[];
    float* sS = sm;                     // 32*SSTRIDE : raw scores -> fused probs (tf32)
    float* sT = sS + 32 * SSTRIDE;      // TBUF : K tile / V tile / 4 partial buffers
    float* sQ = sT + TBUF;              // 32*QS : raw Q

    const uint32_t sTa = (uint32_t)__cvta_generic_to_shared(sT);
    const uint32_t sQa = (uint32_t)__cvta_generic_to_shared(sQ);

    const int t    = threadIdx.x;
    const int lane = t & 31;
    const int wrp  = t >> 5;
    const int gid  = lane >> 2;   // groupID (0..7)
    const int tig  = lane & 3;    // thread-in-group (0..3)

    const int l0 = blockIdx.x * 32;
    const int bh = blockIdx.y;
    const int b  = bh >> 3;
    const int h  = bh & 7;

    const size_t rowstride = (size_t)Hc * Ec;   // 512 floats between seq positions
    const float* Qb = Q + ((size_t)b * Lc) * rowstride + (size_t)h * Ec;
    const float* Kb = K + ((size_t)b * Lc) * rowstride + (size_t)h * Ec;
    const float* Vb = V + ((size_t)b * Lc) * rowstride + (size_t)h * Dc;

    const int sr = t >> 4;              // staging row 0..15
    const int sc = (t & 15) << 2;       // staging col (floats)

    // ---- stage Q (raw fp32, unscaled) + K tile 0 via cp.async ----
    {
        const float* qsrc = Qb + (size_t)(l0 + sr) * rowstride + sc;
        cp16(sQa + (uint32_t)(sr * QS + sc) * 4u, qsrc);
        cp16(sQa + (uint32_t)((sr + 16) * QS + sc) * 4u, qsrc + 16 * rowstride);

        const float* ksrc = Kb + (size_t)sr * rowstride + sc;
        uint32_t kdst = sTa + (uint32_t)(sr * KS + sc) * 4u;
        #pragma unroll
        for (int it = 0; it < 8; it++) {
            cp16(kdst, ksrc);
            kdst += 16 * KS * 4;
            ksrc += 16 * rowstride;
        }
        CP_COMMIT();
    }
    CP_WAIT0();
    __syncthreads();

    // ================= phase 1: S = Q K^T via tf32 mma (raw scores) =================
    const int mb1 = wrp >> 2;
    const int ns0 = (wrp & 3) * 32;

    uint32_t Af[8][4];
    {
        const int ra = mb1 * 16 + gid;
        #pragma unroll
        for (int ks = 0; ks < 8; ks++) {
            int c0 = ks * 8 + tig;
            Af[ks][0] = fbits(sQ[ra * QS + c0]);
            Af[ks][1] = fbits(sQ[(ra + 8) * QS + c0]);
            Af[ks][2] = fbits(sQ[ra * QS + c0 + 4]);
            Af[ks][3] = fbits(sQ[(ra + 8) * QS + c0 + 4]);
        }
    }

    const int nsteps = (l0 >> 7) + 1;   // causal tile skipping

    for (int st = 0; st < nsteps; st++) {
        if (st > 0) {
            __syncthreads();
            const float* ksrc = Kb + (size_t)(st * 128 + sr) * rowstride + sc;
            uint32_t kdst = sTa + (uint32_t)(sr * KS + sc) * 4u;
            #pragma unroll
            for (int it = 0; it < 8; it++) {
                cp16(kdst, ksrc);
                kdst += 16 * KS * 4;
                ksrc += 16 * rowstride;
            }
            CP_COMMIT();
            CP_WAIT0();
            __syncthreads();
        }

        float c[4][4];
        #pragma unroll
        for (int nt = 0; nt < 4; nt++)
            #pragma unroll
            for (int j = 0; j < 4; j++) c[nt][j] = 0.f;

        #pragma unroll
        for (int ks = 0; ks < 8; ks++) {
            #pragma unroll
            for (int nt = 0; nt < 4; nt++) {
                const float* bp = sT + (ns0 + nt * 8 + gid) * KS + ks * 8 + tig;
                mma_tf32(c[nt], Af[ks], fbits(bp[0]), fbits(bp[4]));
            }
        }

        const int r0 = mb1 * 16 + gid;
        #pragma unroll
        for (int nt = 0; nt < 4; nt++) {
            int col = st * 128 + ns0 + nt * 8 + 2 * tig;
            *(float2*)(sS + r0 * SSTRIDE + col)       = make_float2(c[nt][0], c[nt][1]);
            *(float2*)(sS + (r0 + 8) * SSTRIDE + col) = make_float2(c[nt][2], c[nt][3]);
        }
    }
    __syncthreads();

    // ========== phase 2: scaled softmax + Gaussian prior + gated fuse ==========
    const float g = 1.f / (1.f + __expf(-__ldg(gate_logit + h)));
    const float SCL2 = 0.18033688011112043f;   // (1/8) * log2(e)

    for (int rr = wrp; rr < 32; rr += 8) {
        const int l = l0 + rr;
        float* row = sS + rr * SSTRIDE;

        float v[16];
        #pragma unroll
        for (int k = 0; k < 16; k++) v[k] = row[lane + k * 32];

        float m = -1e30f;
        #pragma unroll
        for (int k = 0; k < 16; k++)
            if (lane + k * 32 <= l) m = fmaxf(m, v[k]);
        #pragma unroll
        for (int o = 16; o; o >>= 1) m = fmaxf(m, __shfl_xor_sync(0xffffffffu, m, o));

        float Z = 0.f;
        #pragma unroll
        for (int k = 0; k < 16; k++) {
            float e = (lane + k * 32 <= l) ? exp2f((v[k] - m) * SCL2) : 0.f;
            v[k] = e;
            Z += e;
        }
        #pragma unroll
        for (int o = 16; o; o >>= 1) Z += __shfl_xor_sync(0xffffffffu, Z, o);

        // sig = 3^(sigmoid(5*sigma)+1e-5) - 1
        float sg = sigma[((size_t)b * Lc + l) * Hc + h];
        float sig = 1.f / (1.f + __expf(-5.f * sg)) + 1e-5f;
        sig = exp2f(sig * 1.5849625007211562f) - 1.f;
        const float inv2s2 = 1.f / (2.f * sig * sig);
        const float coef = 0.3989422804014327f / sig;   // 1/(sqrt(2pi)*sig)

        float pv[16];
        float Sp = 0.f;
        #pragma unroll
        for (int k = 0; k < 16; k++) {
            float d = (float)(l - (lane + k * 32));
            pv[k] = __expf(-d * d * inv2s2);
            Sp += pv[k];
        }
        #pragma unroll
        for (int o = 16; o; o >>= 1) Sp += __shfl_xor_sync(0xffffffffu, Sp, o);
        Sp *= coef;

        float Sf = g + (1.f - g) * (Sp / (Sp + 1e-8f));
        float invSf = 1.f / (Sf + 1e-8f);
        float wE = (g / Z) * invSf;
        float wP = ((1.f - g) * coef / (Sp + 1e-8f)) * invSf;

        #pragma unroll
        for (int k = 0; k < 16; k++)
            row[lane + k * 32] =
                __uint_as_float(f2tf32(fmaf(v[k], wE, pv[k] * wP)));
    }

    // ================= phase 3: out = P @ V (m2 x n4, 4-way k-split) =================
    const int kh = wrp >> 1;            // k-quarter within each 128-row tile
    const int n0 = (wrp & 1) * 32;      // column half

    float acc[2][4][4];
    #pragma unroll
    for (int mt = 0; mt < 2; mt++)
        #pragma unroll
        for (int nt = 0; nt < 4; nt++)
            #pragma unroll
            for (int j = 0; j < 4; j++) acc[mt][nt][j] = 0.f;

    for (int st = 0; st < 4; st++) {
        __syncthreads();
        {
            const float* vsrc = Vb + (size_t)(st * 128 + sr) * rowstride + sc;
            uint32_t vdst = sTa + (uint32_t)(sr * VS + sc) * 4u;
            #pragma unroll
            for (int it = 0; it < 8; it++) {
                cp16(vdst, vsrc);
                vdst += 16 * VS * 4;
                vsrc += 16 * rowstride;
            }
            CP_COMMIT();
        }
        CP_WAIT0();
        __syncthreads();

        #pragma unroll
        for (int ks = 0; ks < 4; ks++) {
            const int kk = kh * 32 + ks * 8;   // k-row within tile
            uint32_t a[2][4];
            #pragma unroll
            for (int mt = 0; mt < 2; mt++) {
                const float* ap = sS + (mt * 16 + gid) * SSTRIDE + st * 128 + kk + tig;
                a[mt][0] = fbits(ap[0]);
                a[mt][1] = fbits(ap[8 * SSTRIDE]);
                a[mt][2] = fbits(ap[4]);
                a[mt][3] = fbits(ap[8 * SSTRIDE + 4]);
            }
            #pragma unroll
            for (int nt = 0; nt < 4; nt++) {
                const float* bp = sT + (kk + tig) * VS + n0 + nt * 8 + gid;
                uint32_t b0 = fbits(bp[0]);
                uint32_t b1 = fbits(bp[4 * VS]);
                mma_tf32(acc[0][nt], a[0], b0, b1);
                mma_tf32(acc[1][nt], a[1], b0, b1);
            }
        }
    }

    // 4-way kh reduction through smem, then coalesced store
    __syncthreads();
    {
        float* sR = sT + kh * (32 * VS);
        #pragma unroll
        for (int mt = 0; mt < 2; mt++) {
            const int r0 = mt * 16 + gid;
            #pragma unroll
            for (int nt = 0; nt < 4; nt++) {
                int col = n0 + nt * 8 + 2 * tig;
                *(float2*)(sR + r0 * VS + col) =
                    make_float2(acc[mt][nt][0], acc[mt][nt][1]);
                *(float2*)(sR + (r0 + 8) * VS + col) =
                    make_float2(acc[mt][nt][2], acc[mt][nt][3]);
            }
        }
    }
    __syncthreads();

    for (int i = t; i < 512; i += THREADS) {   // 512 float4 slots = 32x64
        int r = i >> 4, c = (i & 15) << 2;
        const float* p0 = sT + r * VS + c;
        float4 o;
        o.x = p0[0] + p0[32*VS]     + p0[64*VS]     + p0[96*VS];
        o.y = p0[1] + p0[32*VS + 1] + p0[64*VS + 1] + p0[96*VS + 1];
        o.z = p0[2] + p0[32*VS + 2] + p0[64*VS + 2] + p0[96*VS + 2];
        o.w = p0[3] + p0[32*VS + 3] + p0[64*VS + 3] + p0[96*VS + 3];
        *(float4*)(out + (((size_t)b * Lc + (l0 + r)) * Hc + h) * Dc + c) = o;
    }
}

extern "C" void kernel_launch(void* const* d_in, const int* in_sizes, int n_in,
                              void* d_out, int out_size)
{
    const float* Q     = (const float*)d_in[0];
    const float* K     = (const float*)d_in[1];
    const float* V     = (const float*)d_in[2];
    const float* sigma = (const float*)d_in[3];
    const float* gate  = (const float*)d_in[4];
    // d_in[5] = attn_mask: deterministic causal triu(k=1); handled analytically.
    float* out = (float*)d_out;

    const size_t smem = (size_t)(32 * SSTRIDE + TBUF + 32 * QS) * sizeof(float);
    cudaFuncSetAttribute(anomaly_attn_kernel,
                         cudaFuncAttributeMaxDynamicSharedMemorySize, (int)smem);

    dim3 grid(Lc / 32, Bc * Hc);
    anomaly_attn_kernel<<<grid, THREADS, smem>>>(Q, K, V, sigma, gate, out);
}

// round 5
// speedup vs baseline: 11.6566x; 1.0026x over previous
#include <cuda_runtime.h>
#include <cstdint>

// Problem constants (fixed by the reference)
#define Bc 16
#define Lc 512
#define Hc 8
#define Ec 64
#define Dc 64

#define THREADS 256
#define SSTRIDE 516      // score buffer row stride (L + 4)
#define QS 68            // Q tile stride
#define KS 68            // K tile stride   (bank = 4*gid + tig  -> conflict-free B frags)
#define VS 72            // V tile stride   (bank = 8*tig + gid  -> conflict-free B frags)
#define TBUF (128 * VS)  // 9216 floats: K tile / V tile / 4 reduction buffers (32x72)

__device__ __forceinline__ uint32_t f2tf32(float x) {
    uint32_t r;
    asm("cvt.rna.tf32.f32 %0, %1;" : "=r"(r) : "f"(x));
    return r;
}
__device__ __forceinline__ uint32_t fbits(float x) { return __float_as_uint(x); }

__device__ __forceinline__ void mma_tf32(float c[4], const uint32_t a[4],
                                         uint32_t b0, uint32_t b1) {
    asm volatile(
        "mma.sync.aligned.m16n8k8.row.col.f32.tf32.tf32.f32 "
        "{%0,%1,%2,%3}, {%4,%5,%6,%7}, {%8,%9}, {%0,%1,%2,%3};"
        : "+f"(c[0]), "+f"(c[1]), "+f"(c[2]), "+f"(c[3])
        : "r"(a[0]), "r"(a[1]), "r"(a[2]), "r"(a[3]), "r"(b0), "r"(b1));
}

__device__ __forceinline__ void cp16(uint32_t dst, const float* src) {
    asm volatile("cp.async.ca.shared.global [%0], [%1], 16;" :: "r"(dst), "l"(src));
}
#define CP_COMMIT() asm volatile("cp.async.commit_group;")
#define CP_WAIT0()  asm volatile("cp.async.wait_group 0;" ::: "memory")

__global__ __launch_bounds__(THREADS, 2) void anomaly_attn_kernel(
    const float* __restrict__ Q, const float* __restrict__ K,
    const float* __restrict__ V, const float* __restrict__ sigma,
    const float* __restrict__ gate_logit, float* __restrict__ out)
{
    extern __shared__ float sm[];
    float* sS = sm;                     // 32*SSTRIDE : raw scores -> fused probs (tf32)
    float* sT = sS + 32 * SSTRIDE;      // TBUF : K tile / V tile / 4 partial buffers
    float* sQ = sT + TBUF;              // 32*QS : raw Q

    const uint32_t sTa = (uint32_t)__cvta_generic_to_shared(sT);
    const uint32_t sQa = (uint32_t)__cvta_generic_to_shared(sQ);

    const int t    = threadIdx.x;
    const int lane = t & 31;
    const int wrp  = t >> 5;
    const int gid  = lane >> 2;   // groupID (0..7)
    const int tig  = lane & 3;    // thread-in-group (0..3)

    const int l0 = blockIdx.x * 32;
    const int bh = blockIdx.y;
    const int b  = bh >> 3;
    const int h  = bh & 7;

    const size_t rowstride = (size_t)Hc * Ec;   // 512 floats between seq positions
    const float* Qb = Q + ((size_t)b * Lc) * rowstride + (size_t)h * Ec;
    const float* Kb = K + ((size_t)b * Lc) * rowstride + (size_t)h * Ec;
    const float* Vb = V + ((size_t)b * Lc) * rowstride + (size_t)h * Dc;

    const int sr = t >> 4;              // staging row 0..15
    const int sc = (t & 15) << 2;       // staging col (floats)

    // ---- stage Q (raw fp32, unscaled) + K tile 0 via cp.async ----
    {
        const float* qsrc = Qb + (size_t)(l0 + sr) * rowstride + sc;
        cp16(sQa + (uint32_t)(sr * QS + sc) * 4u, qsrc);
        cp16(sQa + (uint32_t)((sr + 16) * QS + sc) * 4u, qsrc + 16 * rowstride);

        const float* ksrc = Kb + (size_t)sr * rowstride + sc;
        uint32_t kdst = sTa + (uint32_t)(sr * KS + sc) * 4u;
        #pragma unroll
        for (int it = 0; it < 8; it++) {
            cp16(kdst, ksrc);
            kdst += 16 * KS * 4;
            ksrc += 16 * rowstride;
        }
        CP_COMMIT();
    }
    CP_WAIT0();
    __syncthreads();

    // ================= phase 1: S = Q K^T via tf32 mma (raw scores) =================
    const int mb1 = wrp >> 2;
    const int ns0 = (wrp & 3) * 32;

    uint32_t Af[8][4];
    {
        const int ra = mb1 * 16 + gid;
        #pragma unroll
        for (int ks = 0; ks < 8; ks++) {
            int c0 = ks * 8 + tig;
            Af[ks][0] = fbits(sQ[ra * QS + c0]);
            Af[ks][1] = fbits(sQ[(ra + 8) * QS + c0]);
            Af[ks][2] = fbits(sQ[ra * QS + c0 + 4]);
            Af[ks][3] = fbits(sQ[(ra + 8) * QS + c0 + 4]);
        }
    }

    const int nsteps = (l0 >> 7) + 1;   // causal tile skipping

    for (int st = 0; st < nsteps; st++) {
        if (st > 0) {
            __syncthreads();
            const float* ksrc = Kb + (size_t)(st * 128 + sr) * rowstride + sc;
            uint32_t kdst = sTa + (uint32_t)(sr * KS + sc) * 4u;
            #pragma unroll
            for (int it = 0; it < 8; it++) {
                cp16(kdst, ksrc);
                kdst += 16 * KS * 4;
                ksrc += 16 * rowstride;
            }
            CP_COMMIT();
            CP_WAIT0();
            __syncthreads();
        }

        float c[4][4];
        #pragma unroll
        for (int nt = 0; nt < 4; nt++)
            #pragma unroll
            for (int j = 0; j < 4; j++) c[nt][j] = 0.f;

        #pragma unroll
        for (int ks = 0; ks < 8; ks++) {
            #pragma unroll
            for (int nt = 0; nt < 4; nt++) {
                const float* bp = sT + (ns0 + nt * 8 + gid) * KS + ks * 8 + tig;
                mma_tf32(c[nt], Af[ks], fbits(bp[0]), fbits(bp[4]));
            }
        }

        const int r0 = mb1 * 16 + gid;
        #pragma unroll
        for (int nt = 0; nt < 4; nt++) {
            int col = st * 128 + ns0 + nt * 8 + 2 * tig;
            *(float2*)(sS + r0 * SSTRIDE + col)       = make_float2(c[nt][0], c[nt][1]);
            *(float2*)(sS + (r0 + 8) * SSTRIDE + col) = make_float2(c[nt][2], c[nt][3]);
        }
    }
    __syncthreads();

    // ========== phase 2: scaled softmax + Gaussian prior + gated fuse ==========
    const float g = 1.f / (1.f + __expf(-__ldg(gate_logit + h)));
    const float SCL2 = 0.18033688011112043f;   // (1/8) * log2(e)

    for (int rr = wrp; rr < 32; rr += 8) {
        const int l = l0 + rr;
        float* row = sS + rr * SSTRIDE;

        float v[16];
        #pragma unroll
        for (int k = 0; k < 16; k++) v[k] = row[lane + k * 32];

        float m = -1e30f;
        #pragma unroll
        for (int k = 0; k < 16; k++)
            if (lane + k * 32 <= l) m = fmaxf(m, v[k]);
        #pragma unroll
        for (int o = 16; o; o >>= 1) m = fmaxf(m, __shfl_xor_sync(0xffffffffu, m, o));

        float Z = 0.f;
        #pragma unroll
        for (int k = 0; k < 16; k++) {
            float e = (lane + k * 32 <= l) ? exp2f((v[k] - m) * SCL2) : 0.f;
            v[k] = e;
            Z += e;
        }
        #pragma unroll
        for (int o = 16; o; o >>= 1) Z += __shfl_xor_sync(0xffffffffu, Z, o);

        // sig = 3^(sigmoid(5*sigma)+1e-5) - 1
        float sg = sigma[((size_t)b * Lc + l) * Hc + h];
        float sig = 1.f / (1.f + __expf(-5.f * sg)) + 1e-5f;
        sig = exp2f(sig * 1.5849625007211562f) - 1.f;
        const float inv2s2 = 1.f / (2.f * sig * sig);
        const float coef = 0.3989422804014327f / sig;   // 1/(sqrt(2pi)*sig)

        float pv[16];
        float Sp = 0.f;
        #pragma unroll
        for (int k = 0; k < 16; k++) {
            float d = (float)(l - (lane + k * 32));
            pv[k] = __expf(-d * d * inv2s2);
            Sp += pv[k];
        }
        #pragma unroll
        for (int o = 16; o; o >>= 1) Sp += __shfl_xor_sync(0xffffffffu, Sp, o);
        Sp *= coef;

        float Sf = g + (1.f - g) * (Sp / (Sp + 1e-8f));
        float invSf = 1.f / (Sf + 1e-8f);
        float wE = (g / Z) * invSf;
        float wP = ((1.f - g) * coef / (Sp + 1e-8f)) * invSf;

        #pragma unroll
        for (int k = 0; k < 16; k++)
            row[lane + k * 32] =
                __uint_as_float(f2tf32(fmaf(v[k], wE, pv[k] * wP)));
    }

    // ================= phase 3: out = P @ V (m2 x n4, 4-way k-split) =================
    const int kh = wrp >> 1;            // k-quarter within each 128-row tile
    const int n0 = (wrp & 1) * 32;      // column half

    float acc[2][4][4];
    #pragma unroll
    for (int mt = 0; mt < 2; mt++)
        #pragma unroll
        for (int nt = 0; nt < 4; nt++)
            #pragma unroll
            for (int j = 0; j < 4; j++) acc[mt][nt][j] = 0.f;

    for (int st = 0; st < 4; st++) {
        __syncthreads();
        {
            const float* vsrc = Vb + (size_t)(st * 128 + sr) * rowstride + sc;
            uint32_t vdst = sTa + (uint32_t)(sr * VS + sc) * 4u;
            #pragma unroll
            for (int it = 0; it < 8; it++) {
                cp16(vdst, vsrc);
                vdst += 16 * VS * 4;
                vsrc += 16 * rowstride;
            }
            CP_COMMIT();
        }
        CP_WAIT0();
        __syncthreads();

        #pragma unroll
        for (int ks = 0; ks < 4; ks++) {
            const int kk = kh * 32 + ks * 8;   // k-row within tile
            uint32_t a[2][4];
            #pragma unroll
            for (int mt = 0; mt < 2; mt++) {
                const float* ap = sS + (mt * 16 + gid) * SSTRIDE + st * 128 + kk + tig;
                a[mt][0] = fbits(ap[0]);
                a[mt][1] = fbits(ap[8 * SSTRIDE]);
                a[mt][2] = fbits(ap[4]);
                a[mt][3] = fbits(ap[8 * SSTRIDE + 4]);
            }
            #pragma unroll
            for (int nt = 0; nt < 4; nt++) {
                const float* bp = sT + (kk + tig) * VS + n0 + nt * 8 + gid;
                uint32_t b0 = fbits(bp[0]);
                uint32_t b1 = fbits(bp[4 * VS]);
                mma_tf32(acc[0][nt], a[0], b0, b1);
                mma_tf32(acc[1][nt], a[1], b0, b1);
            }
        }
    }

    // 4-way kh reduction through smem, then coalesced store
    __syncthreads();
    {
        float* sR = sT + kh * (32 * VS);
        #pragma unroll
        for (int mt = 0; mt < 2; mt++) {
            const int r0 = mt * 16 + gid;
            #pragma unroll
            for (int nt = 0; nt < 4; nt++) {
                int col = n0 + nt * 8 + 2 * tig;
                *(float2*)(sR + r0 * VS + col) =
                    make_float2(acc[mt][nt][0], acc[mt][nt][1]);
                *(float2*)(sR + (r0 + 8) * VS + col) =
                    make_float2(acc[mt][nt][2], acc[mt][nt][3]);
            }
        }
    }
    __syncthreads();

    for (int i = t; i < 512; i += THREADS) {   // 512 float4 slots = 32x64
        int r = i >> 4, c = (i & 15) << 2;
        const float* p0 = sT + r * VS + c;
        float4 o;
        o.x = p0[0] + p0[32*VS]     + p0[64*VS]     + p0[96*VS];
        o.y = p0[1] + p0[32*VS + 1] + p0[64*VS + 1] + p0[96*VS + 1];
        o.z = p0[2] + p0[32*VS + 2] + p0[64*VS + 2] + p0[96*VS + 2];
        o.w = p0[3] + p0[32*VS + 3] + p0[64*VS + 3] + p0[96*VS + 3];
        *(float4*)(out + (((size_t)b * Lc + (l0 + r)) * Hc + h) * Dc + c) = o;
    }
}

extern "C" void kernel_launch(void* const* d_in, const int* in_sizes, int n_in,
                              void* d_out, int out_size)
{
    const float* Q     = (const float*)d_in[0];
    const float* K     = (const float*)d_in[1];
    const float* V     = (const float*)d_in[2];
    const float* sigma = (const float*)d_in[3];
    const float* gate  = (const float*)d_in[4];
    // d_in[5] = attn_mask: deterministic causal triu(k=1); handled analytically.
    float* out = (float*)d_out;

    const size_t smem = (size_t)(32 * SSTRIDE + TBUF + 32 * QS) * sizeof(float);
    cudaFuncSetAttribute(anomaly_attn_kernel,
                         cudaFuncAttributeMaxDynamicSharedMemorySize, (int)smem);

    dim3 grid(Lc / 32, Bc * Hc);
    anomaly_attn_kernel<<<grid, THREADS, smem>>>(Q, K, V, sigma, gate, out);
}